// round 11
// baseline (speedup 1.0000x reference)
#include <cuda_runtime.h>
#include <cuda_bf16.h>
#include <cstdint>

// BahdanauAttention with size-1 attention axis:
//   softmax over length-1 axis == 1.0 -> attention_weights = ones(B,1,1)
//   context = features (bit-exact copy). Score GEMMs are dead code.
//
// SM-kernel copy is converged at 36.4us = 7.38 TB/s = 92% of HBM spec
// (rounds 3-9; v8 accesses regressed via L1tex wavefront replays).
// This round routes the 128 MiB bulk copy through the COPY ENGINE
// (cudaMemcpyAsync DtoD — explicitly allowed and graph-capturable),
// which bypasses the SM LSU/L1tex path entirely. Tiny kernel fills the
// 64 KiB of attention-weight ones.

static constexpr long long Bsz = 16384;
static constexpr long long Dsz = 2048;
static constexpr long long CTX_ELEMS = Bsz * Dsz;          // 33,554,432 floats
static constexpr long long CTX_BYTES = CTX_ELEMS * 4;      // 128 MiB
static constexpr int AW_VECS = (int)(Bsz / 4);             // 4,096 float4

__global__ void __launch_bounds__(256)
ones_fill_kernel(float4* __restrict__ out_aw) {
    int tid = blockIdx.x * 256 + threadIdx.x;
    if (tid < AW_VECS) {
        out_aw[tid] = make_float4(1.f, 1.f, 1.f, 1.f);
    }
}

extern "C" void kernel_launch(void* const* d_in, const int* in_sizes, int n_in,
                              void* d_out, int out_size) {
    const float* features = (const float*)d_in[0];
    float* out = (float*)d_out;

    // Bulk context copy on the copy engine.
    cudaMemcpyAsync(out, features, (size_t)CTX_BYTES, cudaMemcpyDeviceToDevice);

    // Attention weights = ones (16384 floats = 4096 float4).
    float4* out_aw = (float4*)(out + CTX_ELEMS);
    ones_fill_kernel<<<(AW_VECS + 255) / 256, 256>>>(out_aw);
}